// round 1
// baseline (speedup 1.0000x reference)
#include <cuda_runtime.h>
#include <math.h>

#define NN 32768
#define KC 1024
#define DH 512
#define NITERS 150
#define EPS2 2.0e-5f          // 2*eps
#define DEPS2 5.12e-8f        // DH*eps*eps
#define NKTOT ((size_t)NN * KC)

// ---------------- scratch (device globals; no allocations allowed) ----------
__device__ float g_d[(size_t)NN * KC];      // 128 MB distance matrix
__device__ float g_az[NN];
__device__ float g_bm[KC];
__device__ float g_rel[NN * 5];
__device__ float g_rho[NN];
__device__ float g_inv[NN];                 // 1/sigma_z
__device__ float g_colpart[1024 * KC];      // per-block partial column sums of S
__device__ float g_colsum[KC];

// ---------------- kernel 1: row norms -> az (z rows), bm (mu rows) ----------
__global__ void k_rownorm(const float* __restrict__ z, const float* __restrict__ mu) {
    int gw   = (blockIdx.x * blockDim.x + threadIdx.x) >> 5;
    int lane = threadIdx.x & 31;
    if (gw >= NN + KC) return;
    const float* base = (gw < NN) ? (z + (size_t)gw * DH)
                                  : (mu + (size_t)(gw - NN) * DH);
    float s = 0.f, q = 0.f;
#pragma unroll
    for (int i = 0; i < 4; i++) {
        float4 v = *(const float4*)(base + lane * 4 + i * 128);
        s += v.x + v.y + v.z + v.w;
        q += v.x * v.x + v.y * v.y + v.z * v.z + v.w * v.w;
    }
#pragma unroll
    for (int o = 16; o; o >>= 1) {
        s += __shfl_down_sync(0xffffffffu, s, o);
        q += __shfl_down_sync(0xffffffffu, q, o);
    }
    if (lane == 0) {
        if (gw < NN) g_az[gw] = q + EPS2 * s;
        else         g_bm[gw - NN] = q - EPS2 * s + DEPS2;
    }
}

// ---------------- kernel 2: fp32 SGEMM -> d = sqrt(max(az+bm-2*zm, 0)) ------
__global__ __launch_bounds__(256) void k_gemm(const float* __restrict__ z,
                                              const float* __restrict__ mu) {
    __shared__ float As[16][132];
    __shared__ float Bs[16][132];
    const int tid  = threadIdx.x;
    const int bj   = blockIdx.x;   // 0..7   (col tiles of 128)
    const int bi   = blockIdx.y;   // 0..255 (row tiles of 128)
    const int lrow = tid >> 2;           // 0..63
    const int lcol = (tid & 3) << 2;     // 0,4,8,12
    const int tx   = tid & 15;
    const int ty   = tid >> 4;
    const float* zb = z  + (size_t)(bi * 128) * DH;
    const float* mb = mu + (size_t)(bj * 128) * DH;

    float acc[8][8];
#pragma unroll
    for (int m = 0; m < 8; m++)
#pragma unroll
        for (int n = 0; n < 8; n++) acc[m][n] = 0.f;

    for (int k0 = 0; k0 < DH; k0 += 16) {
        float4 a0 = *(const float4*)(zb + (size_t)lrow        * DH + k0 + lcol);
        float4 a1 = *(const float4*)(zb + (size_t)(lrow + 64) * DH + k0 + lcol);
        float4 b0 = *(const float4*)(mb + (size_t)lrow        * DH + k0 + lcol);
        float4 b1 = *(const float4*)(mb + (size_t)(lrow + 64) * DH + k0 + lcol);
        __syncthreads();
        As[lcol + 0][lrow] = a0.x; As[lcol + 1][lrow] = a0.y;
        As[lcol + 2][lrow] = a0.z; As[lcol + 3][lrow] = a0.w;
        As[lcol + 0][lrow + 64] = a1.x; As[lcol + 1][lrow + 64] = a1.y;
        As[lcol + 2][lrow + 64] = a1.z; As[lcol + 3][lrow + 64] = a1.w;
        Bs[lcol + 0][lrow] = b0.x; Bs[lcol + 1][lrow] = b0.y;
        Bs[lcol + 2][lrow] = b0.z; Bs[lcol + 3][lrow] = b0.w;
        Bs[lcol + 0][lrow + 64] = b1.x; Bs[lcol + 1][lrow + 64] = b1.y;
        Bs[lcol + 2][lrow + 64] = b1.z; Bs[lcol + 3][lrow + 64] = b1.w;
        __syncthreads();
#pragma unroll
        for (int kk = 0; kk < 16; kk++) {
            float a[8], b[8];
#pragma unroll
            for (int m = 0; m < 8; m++) a[m] = As[kk][ty * 8 + m];
#pragma unroll
            for (int n = 0; n < 8; n++) b[n] = Bs[kk][tx * 8 + n];
#pragma unroll
            for (int m = 0; m < 8; m++)
#pragma unroll
                for (int n = 0; n < 8; n++)
                    acc[m][n] = fmaf(a[m], b[n], acc[m][n]);
        }
    }

    const int row0 = bi * 128 + ty * 8;
    const int col0 = bj * 128 + tx * 8;
    float bmv[8];
#pragma unroll
    for (int n = 0; n < 8; n++) bmv[n] = g_bm[col0 + n];
#pragma unroll
    for (int m = 0; m < 8; m++) {
        float azv = g_az[row0 + m];
        float* dst = g_d + (size_t)(row0 + m) * KC + col0;
#pragma unroll
        for (int n4 = 0; n4 < 2; n4++) {
            float4 o;
            o.x = sqrtf(fmaxf(azv + bmv[n4 * 4 + 0] - 2.f * acc[m][n4 * 4 + 0], 0.f));
            o.y = sqrtf(fmaxf(azv + bmv[n4 * 4 + 1] - 2.f * acc[m][n4 * 4 + 1], 0.f));
            o.z = sqrtf(fmaxf(azv + bmv[n4 * 4 + 2] - 2.f * acc[m][n4 * 4 + 2], 0.f));
            o.w = sqrtf(fmaxf(azv + bmv[n4 * 4 + 3] - 2.f * acc[m][n4 * 4 + 3], 0.f));
            *(float4*)(dst + n4 * 4) = o;
        }
    }
}

// ---------------- kernel 3: 5 smallest per row (sorted ascending) -----------
__global__ __launch_bounds__(256) void k_top5() {
    const int row = blockIdx.x;
    const int t   = threadIdx.x;
    __shared__ float sv[1024];
    __shared__ float wv[8];
    __shared__ int   wi[8];
    const float* dr = g_d + (size_t)row * KC;
#pragma unroll
    for (int c = 0; c < 4; c++) sv[t + c * 256] = dr[t + c * 256];
    __syncthreads();
    const float INF = __int_as_float(0x7f800000);
    for (int it = 0; it < 5; it++) {
        float bv = INF; int bix = 0;
#pragma unroll
        for (int c = 0; c < 4; c++) {
            int id = t + c * 256;
            float v = sv[id];
            if (v < bv) { bv = v; bix = id; }
        }
#pragma unroll
        for (int o = 16; o; o >>= 1) {
            float ov = __shfl_down_sync(0xffffffffu, bv, o);
            int   oi = __shfl_down_sync(0xffffffffu, bix, o);
            if (ov < bv) { bv = ov; bix = oi; }
        }
        if ((t & 31) == 0) { wv[t >> 5] = bv; wi[t >> 5] = bix; }
        __syncthreads();
        if (t == 0) {
            float fv = wv[0]; int fi = wi[0];
#pragma unroll
            for (int i = 1; i < 8; i++)
                if (wv[i] < fv) { fv = wv[i]; fi = wi[i]; }
            g_rel[row * 5 + it] = fv;
            sv[fi] = INF;
        }
        __syncthreads();
    }
}

// ---------------- kernel 4: 150-step bisection for sigma_z ------------------
__global__ void k_sigma() {
    int i = blockIdx.x * blockDim.x + threadIdx.x;
    if (i >= NN) return;
    float r0 = g_rel[i * 5 + 0];
    float e1 = fmaxf(g_rel[i * 5 + 1] - r0, 0.f);
    float e2 = fmaxf(g_rel[i * 5 + 2] - r0, 0.f);
    float e3 = fmaxf(g_rel[i * 5 + 3] - r0, 0.f);
    float e4 = fmaxf(g_rel[i * 5 + 4] - r0, 0.f);
    float m0 = 0.f, m1 = 10000.f, s = 1.f;
    for (int it = 0; it < NITERS; it++) {
        float inv = 1.f / s;
        float cur = 1.f + expf(-e1 * inv) + expf(-e2 * inv)
                        + expf(-e3 * inv) + expf(-e4 * inv);
        if (cur > 1.5f) m1 = s; else m0 = s;
        s = 0.5f * (m0 + m1);
    }
    g_rho[i] = r0;
    g_inv[i] = 1.f / s;
}

__device__ __forceinline__ float blocksum256(float v, float* red) {
    int lane = threadIdx.x & 31, w = threadIdx.x >> 5;
#pragma unroll
    for (int o = 16; o; o >>= 1) v += __shfl_down_sync(0xffffffffu, v, o);
    if (!lane) red[w] = v;
    __syncthreads();
    float tot = 0.f;
#pragma unroll
    for (int i = 0; i < 8; i++) tot += red[i];
    __syncthreads();
    return tot;
}

// ---------------- kernel 5: W1, S, partial column sums of S -----------------
__global__ __launch_bounds__(256) void k_w1s(float* __restrict__ outW1a,
                                             float* __restrict__ outS,
                                             float* __restrict__ outW1b) {
    const int blk = blockIdx.x;     // 1024 blocks, 32 rows each
    const int t   = threadIdx.x;
    __shared__ float red[8];
    float colacc[4] = {0.f, 0.f, 0.f, 0.f};
    const int row0 = blk * 32;
    for (int r = 0; r < 32; r++) {
        const int row = row0 + r;
        const float rho = g_rho[row];
        const float inv = g_inv[row];
        const float* drow = g_d + (size_t)row * KC;
        float w[4], part = 0.f;
#pragma unroll
        for (int c = 0; c < 4; c++) {
            float dv = drow[t + c * 256];
            float x  = fmaxf(dv - rho, 0.f);
            w[c] = expf(-x * inv);
            part += w[c];
        }
        float rs = blocksum256(part, red);
        float irs = 1.f / rs;
#pragma unroll
        for (int c = 0; c < 4; c++) {
            size_t idx = (size_t)row * KC + t + c * 256;
            float s = w[c] * irs;
            outW1a[idx] = w[c];
            outW1b[idx] = w[c];
            outS[idx]   = s;
            colacc[c]  += s;
        }
    }
#pragma unroll
    for (int c = 0; c < 4; c++)
        g_colpart[(size_t)blk * KC + t + c * 256] = colacc[c];
}

// ---------------- kernel 6: finalize column sums (fixed order) --------------
__global__ void k_colsum() {
    int col = blockIdx.x * blockDim.x + threadIdx.x;
    if (col >= KC) return;
    float s = 0.f;
    for (int b = 0; b < 1024; b++) s += g_colpart[(size_t)b * KC + col];
    g_colsum[col] = s;
}

// ---------------- kernel 7: D = rownorm(S*S / colsum) -----------------------
__global__ __launch_bounds__(256) void k_D(const float* __restrict__ S,
                                           float* __restrict__ outD) {
    const int blk = blockIdx.x;
    const int t   = threadIdx.x;
    __shared__ float cs[1024];
    __shared__ float red[8];
#pragma unroll
    for (int c = 0; c < 4; c++) cs[t + c * 256] = g_colsum[t + c * 256];
    __syncthreads();
    const int row0 = blk * 32;
    for (int r = 0; r < 32; r++) {
        const int row = row0 + r;
        float tv[4], part = 0.f;
#pragma unroll
        for (int c = 0; c < 4; c++) {
            int col = t + c * 256;
            float s = S[(size_t)row * KC + col];
            tv[c] = (s * s) / cs[col];
            part += tv[c];
        }
        float rs = blocksum256(part, red);
        float irs = 1.f / rs;
#pragma unroll
        for (int c = 0; c < 4; c++)
            outD[(size_t)row * KC + t + c * 256] = tv[c] * irs;
    }
}

// ---------------- launch ----------------------------------------------------
extern "C" void kernel_launch(void* const* d_in, const int* in_sizes, int n_in,
                              void* d_out, int out_size) {
    (void)in_sizes; (void)n_in; (void)out_size;
    const float* z  = (const float*)d_in[0];
    const float* mu = (const float*)d_in[1];
    float* out  = (float*)d_out;
    float* oW1a = out;
    float* oS   = out + NKTOT;
    float* oW1b = out + 2 * NKTOT;
    float* oD   = out + 3 * NKTOT;

    k_rownorm<<<(NN + KC + 7) / 8, 256>>>(z, mu);
    k_gemm<<<dim3(8, 256), 256>>>(z, mu);
    k_top5<<<NN, 256>>>();
    k_sigma<<<NN / 256, 256>>>();
    k_w1s<<<1024, 256>>>(oW1a, oS, oW1b);
    k_colsum<<<4, 256>>>();
    k_D<<<1024, 256>>>(oS, oD);
}

// round 9
// speedup vs baseline: 1.4861x; 1.4861x over previous
#include <cuda_runtime.h>
#include <cuda_bf16.h>
#include <cstdint>
#include <math.h>

#define NN 32768
#define KC 1024
#define DH 512
#define NITERS 150
#define EPS2 2.0e-5f          // 2*eps
#define DEPS2 5.12e-8f        // DH*eps*eps
#define NKTOT ((size_t)NN * KC)

// GEMM tiling (mma.sync path)
#define BM 128
#define BN 128
#define KCH 32
#define NKCH (DH / KCH)       // 16
#define SPAD 40               // padded smem row (bf16 elems): 80B stride, ldmatrix conflict-free

// ---------------- scratch (device globals; no allocations allowed) ----------
__device__ float g_d[(size_t)NN * KC];      // 128 MB distance matrix
__device__ float g_az[NN];
__device__ float g_bm[KC];
__device__ float g_rel[NN * 5];
__device__ float g_rho[NN];
__device__ float g_inv[NN];
__device__ float g_colpart[1024 * KC];
__device__ float g_colsum[KC];
__device__ __nv_bfloat16 g_zhi[(size_t)NN * DH];
__device__ __nv_bfloat16 g_zlo[(size_t)NN * DH];
__device__ __nv_bfloat16 g_mhi[(size_t)KC * DH];
__device__ __nv_bfloat16 g_mlo[(size_t)KC * DH];

// ---------------- PTX helpers ------------------------------------------------
__device__ __forceinline__ uint32_t smem_u32(const void* p) {
    uint32_t a;
    asm("{ .reg .u64 t; cvta.to.shared.u64 t, %1; cvt.u32.u64 %0, t; }"
        : "=r"(a) : "l"(p));
    return a;
}

#define LDSM_X4(r0, r1, r2, r3, addr) \
    asm volatile("ldmatrix.sync.aligned.m8n8.x4.shared.b16 {%0,%1,%2,%3}, [%4];" \
                 : "=r"(r0), "=r"(r1), "=r"(r2), "=r"(r3) : "r"(addr))

#define MMA16816(d, a, b) \
    asm volatile("mma.sync.aligned.m16n8k16.row.col.f32.bf16.bf16.f32 " \
                 "{%0,%1,%2,%3}, {%4,%5,%6,%7}, {%8,%9}, {%0,%1,%2,%3};" \
                 : "+f"((d)[0]), "+f"((d)[1]), "+f"((d)[2]), "+f"((d)[3]) \
                 : "r"((a)[0]), "r"((a)[1]), "r"((a)[2]), "r"((a)[3]), \
                   "r"((b)[0]), "r"((b)[1]))

// ---------------- kernel 1: row norms -> az, bm -----------------------------
__global__ void k_rownorm(const float* __restrict__ z, const float* __restrict__ mu) {
    int gw   = (blockIdx.x * blockDim.x + threadIdx.x) >> 5;
    int lane = threadIdx.x & 31;
    if (gw >= NN + KC) return;
    const float* base = (gw < NN) ? (z + (size_t)gw * DH)
                                  : (mu + (size_t)(gw - NN) * DH);
    float s = 0.f, q = 0.f;
#pragma unroll
    for (int i = 0; i < 4; i++) {
        float4 v = *(const float4*)(base + lane * 4 + i * 128);
        s += v.x + v.y + v.z + v.w;
        q += v.x * v.x + v.y * v.y + v.z * v.z + v.w * v.w;
    }
#pragma unroll
    for (int o = 16; o; o >>= 1) {
        s += __shfl_down_sync(0xffffffffu, s, o);
        q += __shfl_down_sync(0xffffffffu, q, o);
    }
    if (lane == 0) {
        if (gw < NN) g_az[gw] = q + EPS2 * s;
        else         g_bm[gw - NN] = q - EPS2 * s + DEPS2;
    }
}

// ---------------- kernel 1b: bf16 hi/lo split --------------------------------
__global__ void k_split(const float* __restrict__ z, const float* __restrict__ mu) {
    const size_t NZ4 = (size_t)NN * DH / 4;
    const size_t NM4 = (size_t)KC * DH / 4;
    size_t i = (size_t)blockIdx.x * blockDim.x + threadIdx.x;
    if (i >= NZ4 + NM4) return;
    float4 v;
    __nv_bfloat16* hdst;
    __nv_bfloat16* ldst;
    size_t off;
    if (i < NZ4) { v = ((const float4*)z)[i];  hdst = g_zhi; ldst = g_zlo; off = i * 4; }
    else { v = ((const float4*)mu)[i - NZ4]; hdst = g_mhi; ldst = g_mlo; off = (i - NZ4) * 4; }
    float x[4] = {v.x, v.y, v.z, v.w};
    uint32_t hp[2], lp[2];
#pragma unroll
    for (int p = 0; p < 2; p++) {
        __nv_bfloat16 h0 = __float2bfloat16(x[p * 2 + 0]);
        __nv_bfloat16 h1 = __float2bfloat16(x[p * 2 + 1]);
        __nv_bfloat16 l0 = __float2bfloat16(x[p * 2 + 0] - __bfloat162float(h0));
        __nv_bfloat16 l1 = __float2bfloat16(x[p * 2 + 1] - __bfloat162float(h1));
        hp[p] = (uint32_t)__bfloat16_as_ushort(h0) | ((uint32_t)__bfloat16_as_ushort(h1) << 16);
        lp[p] = (uint32_t)__bfloat16_as_ushort(l0) | ((uint32_t)__bfloat16_as_ushort(l1) << 16);
    }
    *(uint2*)(hdst + off) = make_uint2(hp[0], hp[1]);
    *(uint2*)(ldst + off) = make_uint2(lp[0], lp[1]);
}

// ---------------- kernel 2: bf16 3-term mma.sync GEMM -> d -------------------
// CTA 128x128, 8 warps (2x4), warp tile 64x32, K chunks of 32.
__global__ __launch_bounds__(256, 2) void k_gemm_mma() {
    __shared__ __align__(16) __nv_bfloat16 sAh[BM * SPAD];
    __shared__ __align__(16) __nv_bfloat16 sAl[BM * SPAD];
    __shared__ __align__(16) __nv_bfloat16 sBh[BN * SPAD];
    __shared__ __align__(16) __nv_bfloat16 sBl[BN * SPAD];

    const int tid  = threadIdx.x;
    const int wid  = tid >> 5;
    const int lane = tid & 31;
    const int bj   = blockIdx.x;   // 0..7  col tiles
    const int bi   = blockIdx.y;   // 0..255 row tiles
    const int wm   = wid >> 2;     // 0..1
    const int wn   = wid & 3;      // 0..3

    const __nv_bfloat16* zh = g_zhi + (size_t)(bi * BM) * DH;
    const __nv_bfloat16* zl = g_zlo + (size_t)(bi * BM) * DH;
    const __nv_bfloat16* mh = g_mhi + (size_t)(bj * BN) * DH;
    const __nv_bfloat16* ml = g_mlo + (size_t)(bj * BN) * DH;

    const uint32_t sAh32 = smem_u32(sAh);
    const uint32_t sAl32 = smem_u32(sAl);
    const uint32_t sBh32 = smem_u32(sBh);
    const uint32_t sBl32 = smem_u32(sBl);

    float acc[4][4][4];
#pragma unroll
    for (int mt = 0; mt < 4; mt++)
#pragma unroll
        for (int nt = 0; nt < 4; nt++)
#pragma unroll
            for (int e = 0; e < 4; e++) acc[mt][nt][e] = 0.f;

    const int lr = tid >> 1;          // load row 0..127
    const int lc = (tid & 1) * 16;    // load col segment (16 bf16)

    for (int kc = 0; kc < NKCH; kc++) {
        const int kof = kc * KCH;
        __syncthreads();
        {
            const size_t go = (size_t)lr * DH + kof + lc;
            const int so = lr * SPAD + lc;
            *(uint4*)&sAh[so]     = *(const uint4*)&zh[go];
            *(uint4*)&sAh[so + 8] = *(const uint4*)&zh[go + 8];
            *(uint4*)&sAl[so]     = *(const uint4*)&zl[go];
            *(uint4*)&sAl[so + 8] = *(const uint4*)&zl[go + 8];
            *(uint4*)&sBh[so]     = *(const uint4*)&mh[go];
            *(uint4*)&sBh[so + 8] = *(const uint4*)&mh[go + 8];
            *(uint4*)&sBl[so]     = *(const uint4*)&ml[go];
            *(uint4*)&sBl[so + 8] = *(const uint4*)&ml[go + 8];
        }
        __syncthreads();

#pragma unroll
        for (int combo = 0; combo < 3; combo++) {
            const uint32_t aBase = (combo < 2) ? sAh32 : sAl32;
            const uint32_t bBase = (combo == 1) ? sBl32 : sBh32;
#pragma unroll
            for (int k16 = 0; k16 < KCH; k16 += 16) {
                uint32_t af[4][4];
#pragma unroll
                for (int mt = 0; mt < 4; mt++) {
                    const int mrow = wm * 64 + mt * 16 + (lane & 15);
                    const int mcol = k16 + (lane >> 4) * 8;
                    LDSM_X4(af[mt][0], af[mt][1], af[mt][2], af[mt][3],
                            aBase + (uint32_t)(mrow * SPAD + mcol) * 2);
                }
                uint32_t bf[4][2];
#pragma unroll
                for (int np = 0; np < 2; np++) {
                    const int nrow = wn * 32 + np * 16 + (lane & 7) + ((lane >> 4) & 1) * 8;
                    const int ncol = k16 + ((lane >> 3) & 1) * 8;
                    uint32_t q0, q1, q2, q3;
                    LDSM_X4(q0, q1, q2, q3,
                            bBase + (uint32_t)(nrow * SPAD + ncol) * 2);
                    bf[np * 2 + 0][0] = q0; bf[np * 2 + 0][1] = q1;
                    bf[np * 2 + 1][0] = q2; bf[np * 2 + 1][1] = q3;
                }
#pragma unroll
                for (int mt = 0; mt < 4; mt++)
#pragma unroll
                    for (int nt = 0; nt < 4; nt++)
                        MMA16816(acc[mt][nt], af[mt], bf[nt]);
            }
        }
    }

    // epilogue: d = sqrt(max(az + bm - 2*acc, 0))
    const int g  = lane >> 2;
    const int nc = (lane & 3) * 2;
    const int row0 = bi * BM + wm * 64;
    const int col0 = bj * BN + wn * 32;
#pragma unroll
    for (int mt = 0; mt < 4; mt++) {
        const int r0 = row0 + mt * 16 + g;
        const int r1 = r0 + 8;
        const float az0 = g_az[r0];
        const float az1 = g_az[r1];
#pragma unroll
        for (int nt = 0; nt < 4; nt++) {
            const int c = col0 + nt * 8 + nc;
            const float bm0 = g_bm[c];
            const float bm1 = g_bm[c + 1];
            const float* a = acc[mt][nt];
            float2 o0, o1;
            o0.x = sqrtf(fmaxf(az0 + bm0 - 2.f * a[0], 0.f));
            o0.y = sqrtf(fmaxf(az0 + bm1 - 2.f * a[1], 0.f));
            o1.x = sqrtf(fmaxf(az1 + bm0 - 2.f * a[2], 0.f));
            o1.y = sqrtf(fmaxf(az1 + bm1 - 2.f * a[3], 0.f));
            *(float2*)(g_d + (size_t)r0 * KC + c) = o0;
            *(float2*)(g_d + (size_t)r1 * KC + c) = o1;
        }
    }
}

// ---------------- kernel 3: 5 smallest per row ------------------------------
__global__ __launch_bounds__(256) void k_top5() {
    const int row = blockIdx.x;
    const int t   = threadIdx.x;
    __shared__ float sv[1024];
    __shared__ float wv[8];
    __shared__ int   wi[8];
    const float* dr = g_d + (size_t)row * KC;
#pragma unroll
    for (int c = 0; c < 4; c++) sv[t + c * 256] = dr[t + c * 256];
    __syncthreads();
    const float INF = __int_as_float(0x7f800000);
    for (int it = 0; it < 5; it++) {
        float bv = INF; int bix = 0;
#pragma unroll
        for (int c = 0; c < 4; c++) {
            int id = t + c * 256;
            float v = sv[id];
            if (v < bv) { bv = v; bix = id; }
        }
#pragma unroll
        for (int o = 16; o; o >>= 1) {
            float ov = __shfl_down_sync(0xffffffffu, bv, o);
            int   oi = __shfl_down_sync(0xffffffffu, bix, o);
            if (ov < bv) { bv = ov; bix = oi; }
        }
        if ((t & 31) == 0) { wv[t >> 5] = bv; wi[t >> 5] = bix; }
        __syncthreads();
        if (t == 0) {
            float fv = wv[0]; int fi = wi[0];
#pragma unroll
            for (int i = 1; i < 8; i++)
                if (wv[i] < fv) { fv = wv[i]; fi = wi[i]; }
            g_rel[row * 5 + it] = fv;
            sv[fi] = INF;
        }
        __syncthreads();
    }
}

// ---------------- kernel 4: bisection for sigma_z ---------------------------
__global__ void k_sigma() {
    int i = blockIdx.x * blockDim.x + threadIdx.x;
    if (i >= NN) return;
    float r0 = g_rel[i * 5 + 0];
    float e1 = fmaxf(g_rel[i * 5 + 1] - r0, 0.f);
    float e2 = fmaxf(g_rel[i * 5 + 2] - r0, 0.f);
    float e3 = fmaxf(g_rel[i * 5 + 3] - r0, 0.f);
    float e4 = fmaxf(g_rel[i * 5 + 4] - r0, 0.f);
    float m0 = 0.f, m1 = 10000.f, s = 1.f;
    for (int it = 0; it < NITERS; it++) {
        float inv = 1.f / s;
        float cur = 1.f + expf(-e1 * inv) + expf(-e2 * inv)
                        + expf(-e3 * inv) + expf(-e4 * inv);
        if (cur > 1.5f) m1 = s; else m0 = s;
        s = 0.5f * (m0 + m1);
    }
    g_rho[i] = r0;
    g_inv[i] = 1.f / s;
}

__device__ __forceinline__ float blocksum256(float v, float* red) {
    int lane = threadIdx.x & 31, w = threadIdx.x >> 5;
#pragma unroll
    for (int o = 16; o; o >>= 1) v += __shfl_down_sync(0xffffffffu, v, o);
    if (!lane) red[w] = v;
    __syncthreads();
    float tot = 0.f;
#pragma unroll
    for (int i = 0; i < 8; i++) tot += red[i];
    __syncthreads();
    return tot;
}

// ---------------- kernel 5: W1, S, partial column sums of S -----------------
__global__ __launch_bounds__(256) void k_w1s(float* __restrict__ outW1a,
                                             float* __restrict__ outS,
                                             float* __restrict__ outW1b) {
    const int blk = blockIdx.x;
    const int t   = threadIdx.x;
    __shared__ float red[8];
    float colacc[4] = {0.f, 0.f, 0.f, 0.f};
    const int row0 = blk * 32;
    for (int r = 0; r < 32; r++) {
        const int row = row0 + r;
        const float rho = g_rho[row];
        const float inv = g_inv[row];
        const float* drow = g_d + (size_t)row * KC;
        float w[4], part = 0.f;
#pragma unroll
        for (int c = 0; c < 4; c++) {
            float dv = drow[t + c * 256];
            float x  = fmaxf(dv - rho, 0.f);
            w[c] = expf(-x * inv);
            part += w[c];
        }
        float rs = blocksum256(part, red);
        float irs = 1.f / rs;
#pragma unroll
        for (int c = 0; c < 4; c++) {
            size_t idx = (size_t)row * KC + t + c * 256;
            float s = w[c] * irs;
            outW1a[idx] = w[c];
            outW1b[idx] = w[c];
            outS[idx]   = s;
            colacc[c]  += s;
        }
    }
#pragma unroll
    for (int c = 0; c < 4; c++)
        g_colpart[(size_t)blk * KC + t + c * 256] = colacc[c];
}

// ---------------- kernel 6: finalize column sums ----------------------------
__global__ void k_colsum() {
    int col = blockIdx.x * blockDim.x + threadIdx.x;
    if (col >= KC) return;
    float s = 0.f;
    for (int b = 0; b < 1024; b++) s += g_colpart[(size_t)b * KC + col];
    g_colsum[col] = s;
}

// ---------------- kernel 7: D = rownorm(S*S / colsum) -----------------------
__global__ __launch_bounds__(256) void k_D(const float* __restrict__ S,
                                           float* __restrict__ outD) {
    const int blk = blockIdx.x;
    const int t   = threadIdx.x;
    __shared__ float cs[1024];
    __shared__ float red[8];
#pragma unroll
    for (int c = 0; c < 4; c++) cs[t + c * 256] = g_colsum[t + c * 256];
    __syncthreads();
    const int row0 = blk * 32;
    for (int r = 0; r < 32; r++) {
        const int row = row0 + r;
        float tv[4], part = 0.f;
#pragma unroll
        for (int c = 0; c < 4; c++) {
            int col = t + c * 256;
            float s = S[(size_t)row * KC + col];
            tv[c] = (s * s) / cs[col];
            part += tv[c];
        }
        float rs = blocksum256(part, red);
        float irs = 1.f / rs;
#pragma unroll
        for (int c = 0; c < 4; c++)
            outD[(size_t)row * KC + t + c * 256] = tv[c] * irs;
    }
}

// ---------------- launch ----------------------------------------------------
extern "C" void kernel_launch(void* const* d_in, const int* in_sizes, int n_in,
                              void* d_out, int out_size) {
    (void)in_sizes; (void)n_in; (void)out_size;
    const float* z  = (const float*)d_in[0];
    const float* mu = (const float*)d_in[1];
    float* out  = (float*)d_out;
    float* oW1a = out;
    float* oS   = out + NKTOT;
    float* oW1b = out + 2 * NKTOT;
    float* oD   = out + 3 * NKTOT;

    k_rownorm<<<(NN + KC + 7) / 8, 256>>>(z, mu);
    {
        const size_t tot4 = ((size_t)NN * DH + (size_t)KC * DH) / 4;
        k_split<<<(unsigned)((tot4 + 255) / 256), 256>>>(z, mu);
    }
    k_gemm_mma<<<dim3(KC / BN, NN / BM), 256>>>();
    k_top5<<<NN, 256>>>();
    k_sigma<<<NN / 256, 256>>>();
    k_w1s<<<1024, 256>>>(oW1a, oS, oW1b);
    k_colsum<<<4, 256>>>();
    k_D<<<1024, 256>>>(oS, oD);
}

// round 10
// speedup vs baseline: 1.6874x; 1.1355x over previous
#include <cuda_runtime.h>
#include <cuda_bf16.h>
#include <cstdint>
#include <math.h>

#define NN 32768
#define KC 1024
#define DH 512
#define NITERS 150
#define EPS2 2.0e-5f
#define DEPS2 5.12e-8f
#define NKTOT ((size_t)NN * KC)

// GEMM tiling (mma.sync + cp.async double-buffer)
#define BM 128
#define BN 128
#define KCH 32
#define NKCH (DH / KCH)       // 16
#define SPAD 40               // padded smem row stride (bf16): 80B, ldmatrix conflict-free
#define ABYTES 10240          // one array: 128*40*2
#define BUFBYTES 40960        // Ah,Al,Bh,Bl
#define SMEM_GEMM (2 * BUFBYTES)

// ---------------- scratch ----------------------------------------------------
__device__ float g_d[(size_t)NN * KC];
__device__ float g_az[NN];
__device__ float g_bm[KC];
__device__ float g_rel[NN * 5];
__device__ float g_rho[NN];
__device__ float g_inv[NN];
__device__ float g_colpart[1024 * KC];
__device__ float g_colsum[KC];
__device__ __nv_bfloat16 g_zhi[(size_t)NN * DH];
__device__ __nv_bfloat16 g_zlo[(size_t)NN * DH];
__device__ __nv_bfloat16 g_mhi[(size_t)KC * DH];
__device__ __nv_bfloat16 g_mlo[(size_t)KC * DH];

// ---------------- PTX helpers -------------------------------------------------
__device__ __forceinline__ uint32_t smem_u32(const void* p) {
    uint32_t a;
    asm("{ .reg .u64 t; cvta.to.shared.u64 t, %1; cvt.u32.u64 %0, t; }"
        : "=r"(a) : "l"(p));
    return a;
}
#define LDSM_X4(r0, r1, r2, r3, addr) \
    asm volatile("ldmatrix.sync.aligned.m8n8.x4.shared.b16 {%0,%1,%2,%3}, [%4];" \
                 : "=r"(r0), "=r"(r1), "=r"(r2), "=r"(r3) : "r"(addr))
#define MMA16816(d, a, b) \
    asm volatile("mma.sync.aligned.m16n8k16.row.col.f32.bf16.bf16.f32 " \
                 "{%0,%1,%2,%3}, {%4,%5,%6,%7}, {%8,%9}, {%0,%1,%2,%3};" \
                 : "+f"((d)[0]), "+f"((d)[1]), "+f"((d)[2]), "+f"((d)[3]) \
                 : "r"((a)[0]), "r"((a)[1]), "r"((a)[2]), "r"((a)[3]), \
                   "r"((b)[0]), "r"((b)[1]))
#define CP16(dst, src) \
    asm volatile("cp.async.cg.shared.global [%0], [%1], 16;" :: "r"(dst), "l"(src))
#define CP_COMMIT() asm volatile("cp.async.commit_group;")
#define CP_WAIT1()  asm volatile("cp.async.wait_group 1;")
#define CP_WAIT0()  asm volatile("cp.async.wait_group 0;")

// ---------------- kernel 1: fused rownorm + hi/lo split ----------------------
__global__ void k_prep(const float* __restrict__ z, const float* __restrict__ mu) {
    int gw   = (blockIdx.x * blockDim.x + threadIdx.x) >> 5;
    int lane = threadIdx.x & 31;
    if (gw >= NN + KC) return;
    const bool isZ = gw < NN;
    const int r = isZ ? gw : gw - NN;
    const float* base = isZ ? (z + (size_t)r * DH) : (mu + (size_t)r * DH);
    __nv_bfloat16* hd = isZ ? (g_zhi + (size_t)r * DH) : (g_mhi + (size_t)r * DH);
    __nv_bfloat16* ld = isZ ? (g_zlo + (size_t)r * DH) : (g_mlo + (size_t)r * DH);
    float s = 0.f, q = 0.f;
#pragma unroll
    for (int i = 0; i < 4; i++) {
        const int off = lane * 4 + i * 128;
        float4 v = *(const float4*)(base + off);
        s += v.x + v.y + v.z + v.w;
        q += v.x * v.x + v.y * v.y + v.z * v.z + v.w * v.w;
        float x[4] = {v.x, v.y, v.z, v.w};
        uint32_t hp[2], lp[2];
#pragma unroll
        for (int p = 0; p < 2; p++) {
            __nv_bfloat16 h0 = __float2bfloat16(x[p * 2 + 0]);
            __nv_bfloat16 h1 = __float2bfloat16(x[p * 2 + 1]);
            __nv_bfloat16 l0 = __float2bfloat16(x[p * 2 + 0] - __bfloat162float(h0));
            __nv_bfloat16 l1 = __float2bfloat16(x[p * 2 + 1] - __bfloat162float(h1));
            hp[p] = (uint32_t)__bfloat16_as_ushort(h0) | ((uint32_t)__bfloat16_as_ushort(h1) << 16);
            lp[p] = (uint32_t)__bfloat16_as_ushort(l0) | ((uint32_t)__bfloat16_as_ushort(l1) << 16);
        }
        *(uint2*)(hd + off) = make_uint2(hp[0], hp[1]);
        *(uint2*)(ld + off) = make_uint2(lp[0], lp[1]);
    }
#pragma unroll
    for (int o = 16; o; o >>= 1) {
        s += __shfl_down_sync(0xffffffffu, s, o);
        q += __shfl_down_sync(0xffffffffu, q, o);
    }
    if (lane == 0) {
        if (isZ) g_az[r] = q + EPS2 * s;
        else     g_bm[r] = q - EPS2 * s + DEPS2;
    }
}

// ---------------- kernel 2: bf16 3-term mma.sync GEMM, cp.async pipelined ----
__global__ __launch_bounds__(256, 2) void k_gemm_mma() {
    extern __shared__ __align__(16) char smem[];
    const uint32_t sb = smem_u32(smem);

    const int tid  = threadIdx.x;
    const int wid  = tid >> 5;
    const int lane = tid & 31;
    const int bj   = blockIdx.x;
    const int bi   = blockIdx.y;
    const int wm   = wid >> 2;
    const int wn   = wid & 3;

    const __nv_bfloat16* zh = g_zhi + (size_t)(bi * BM) * DH;
    const __nv_bfloat16* zl = g_zlo + (size_t)(bi * BM) * DH;
    const __nv_bfloat16* mh = g_mhi + (size_t)(bj * BN) * DH;
    const __nv_bfloat16* ml = g_mlo + (size_t)(bj * BN) * DH;

    float acc[4][4][4];
#pragma unroll
    for (int mt = 0; mt < 4; mt++)
#pragma unroll
        for (int nt = 0; nt < 4; nt++)
#pragma unroll
            for (int e = 0; e < 4; e++) acc[mt][nt][e] = 0.f;

    const int lr = tid >> 1;
    const int lc = (tid & 1) * 16;
    const uint32_t soRow = (uint32_t)(lr * SPAD + lc) * 2;

    // prologue: load chunk 0 into buffer 0
    {
        const size_t go = (size_t)lr * DH + lc;
        const uint32_t d = sb + soRow;
        CP16(d +            0, zh + go); CP16(d +            16, zh + go + 8);
        CP16(d + ABYTES +   0, zl + go); CP16(d + ABYTES +   16, zl + go + 8);
        CP16(d + 2*ABYTES + 0, mh + go); CP16(d + 2*ABYTES + 16, mh + go + 8);
        CP16(d + 3*ABYTES + 0, ml + go); CP16(d + 3*ABYTES + 16, ml + go + 8);
        CP_COMMIT();
    }

    for (int kc = 0; kc < NKCH; kc++) {
        const int b = kc & 1;
        if (kc + 1 < NKCH) {
            const size_t go = (size_t)lr * DH + (kc + 1) * KCH + lc;
            const uint32_t d = sb + (1 - b) * BUFBYTES + soRow;
            CP16(d +            0, zh + go); CP16(d +            16, zh + go + 8);
            CP16(d + ABYTES +   0, zl + go); CP16(d + ABYTES +   16, zl + go + 8);
            CP16(d + 2*ABYTES + 0, mh + go); CP16(d + 2*ABYTES + 16, mh + go + 8);
            CP16(d + 3*ABYTES + 0, ml + go); CP16(d + 3*ABYTES + 16, ml + go + 8);
            CP_COMMIT();
            CP_WAIT1();
        } else {
            CP_WAIT0();
        }
        __syncthreads();

        const uint32_t bufBase = sb + b * BUFBYTES;
#pragma unroll
        for (int combo = 0; combo < 3; combo++) {
            const uint32_t aBase = bufBase + ((combo < 2) ? 0u : (uint32_t)ABYTES);
            const uint32_t bBase = bufBase + ((combo == 1) ? 3u : 2u) * (uint32_t)ABYTES;
#pragma unroll
            for (int k16 = 0; k16 < KCH; k16 += 16) {
                uint32_t af[4][4];
#pragma unroll
                for (int mt = 0; mt < 4; mt++) {
                    const int mrow = wm * 64 + mt * 16 + (lane & 15);
                    const int mcol = k16 + (lane >> 4) * 8;
                    LDSM_X4(af[mt][0], af[mt][1], af[mt][2], af[mt][3],
                            aBase + (uint32_t)(mrow * SPAD + mcol) * 2);
                }
                uint32_t bf[4][2];
#pragma unroll
                for (int np = 0; np < 2; np++) {
                    const int nrow = wn * 32 + np * 16 + (lane & 7) + ((lane >> 4) & 1) * 8;
                    const int ncol = k16 + ((lane >> 3) & 1) * 8;
                    uint32_t q0, q1, q2, q3;
                    LDSM_X4(q0, q1, q2, q3,
                            bBase + (uint32_t)(nrow * SPAD + ncol) * 2);
                    bf[np * 2 + 0][0] = q0; bf[np * 2 + 0][1] = q1;
                    bf[np * 2 + 1][0] = q2; bf[np * 2 + 1][1] = q3;
                }
#pragma unroll
                for (int mt = 0; mt < 4; mt++)
#pragma unroll
                    for (int nt = 0; nt < 4; nt++)
                        MMA16816(acc[mt][nt], af[mt], bf[nt]);
            }
        }
        __syncthreads();
    }

    // epilogue: d = sqrt(max(az + bm - 2*acc, 0))
    const int g  = lane >> 2;
    const int nc = (lane & 3) * 2;
    const int row0 = bi * BM + wm * 64;
    const int col0 = bj * BN + wn * 32;
#pragma unroll
    for (int mt = 0; mt < 4; mt++) {
        const int r0 = row0 + mt * 16 + g;
        const int r1 = r0 + 8;
        const float az0 = g_az[r0];
        const float az1 = g_az[r1];
#pragma unroll
        for (int nt = 0; nt < 4; nt++) {
            const int c = col0 + nt * 8 + nc;
            const float bm0 = g_bm[c];
            const float bm1 = g_bm[c + 1];
            const float* a = acc[mt][nt];
            float2 o0, o1;
            o0.x = sqrtf(fmaxf(az0 + bm0 - 2.f * a[0], 0.f));
            o0.y = sqrtf(fmaxf(az0 + bm1 - 2.f * a[1], 0.f));
            o1.x = sqrtf(fmaxf(az1 + bm0 - 2.f * a[2], 0.f));
            o1.y = sqrtf(fmaxf(az1 + bm1 - 2.f * a[3], 0.f));
            *(float2*)(g_d + (size_t)r0 * KC + c) = o0;
            *(float2*)(g_d + (size_t)r1 * KC + c) = o1;
        }
    }
}

// ---------------- top-5 insertion helper -------------------------------------
__device__ __forceinline__ void ins5(float v, float& t0, float& t1, float& t2,
                                     float& t3, float& t4) {
    if (v < t4) {
        if (v < t3) {
            t4 = t3;
            if (v < t2) {
                t3 = t2;
                if (v < t1) {
                    t2 = t1;
                    if (v < t0) { t1 = t0; t0 = v; } else t1 = v;
                } else t2 = v;
            } else t3 = v;
        } else t4 = v;
    }
}

// ---------------- kernel 3: 5 smallest per row (warp per row) ----------------
__global__ __launch_bounds__(256) void k_top5() {
    const int row  = (blockIdx.x * blockDim.x + threadIdx.x) >> 5;
    const int lane = threadIdx.x & 31;
    const float INF = __int_as_float(0x7f800000);
    const float4* dr = (const float4*)(g_d + (size_t)row * KC);
    float t0 = INF, t1 = INF, t2 = INF, t3 = INF, t4 = INF;
#pragma unroll
    for (int i = 0; i < 8; i++) {
        float4 v = dr[lane + i * 32];
        ins5(v.x, t0, t1, t2, t3, t4);
        ins5(v.y, t0, t1, t2, t3, t4);
        ins5(v.z, t0, t1, t2, t3, t4);
        ins5(v.w, t0, t1, t2, t3, t4);
    }
#pragma unroll
    for (int o = 16; o; o >>= 1) {
        float b0 = __shfl_down_sync(0xffffffffu, t0, o);
        float b1 = __shfl_down_sync(0xffffffffu, t1, o);
        float b2 = __shfl_down_sync(0xffffffffu, t2, o);
        float b3 = __shfl_down_sync(0xffffffffu, t3, o);
        float b4 = __shfl_down_sync(0xffffffffu, t4, o);
        ins5(b0, t0, t1, t2, t3, t4);
        ins5(b1, t0, t1, t2, t3, t4);
        ins5(b2, t0, t1, t2, t3, t4);
        ins5(b3, t0, t1, t2, t3, t4);
        ins5(b4, t0, t1, t2, t3, t4);
    }
    if (lane == 0) {
        g_rel[row * 5 + 0] = t0;
        g_rel[row * 5 + 1] = t1;
        g_rel[row * 5 + 2] = t2;
        g_rel[row * 5 + 3] = t3;
        g_rel[row * 5 + 4] = t4;
    }
}

// ---------------- kernel 4: bisection for sigma_z ----------------------------
__global__ void k_sigma() {
    int i = blockIdx.x * blockDim.x + threadIdx.x;
    if (i >= NN) return;
    float r0 = g_rel[i * 5 + 0];
    float e1 = fmaxf(g_rel[i * 5 + 1] - r0, 0.f);
    float e2 = fmaxf(g_rel[i * 5 + 2] - r0, 0.f);
    float e3 = fmaxf(g_rel[i * 5 + 3] - r0, 0.f);
    float e4 = fmaxf(g_rel[i * 5 + 4] - r0, 0.f);
    float m0 = 0.f, m1 = 10000.f, s = 1.f;
    for (int it = 0; it < NITERS; it++) {
        float inv = 1.f / s;
        float cur = 1.f + expf(-e1 * inv) + expf(-e2 * inv)
                        + expf(-e3 * inv) + expf(-e4 * inv);
        if (cur > 1.5f) m1 = s; else m0 = s;
        s = 0.5f * (m0 + m1);
    }
    g_rho[i] = r0;
    g_inv[i] = 1.f / s;
}

__device__ __forceinline__ float blocksum256(float v, float* red) {
    int lane = threadIdx.x & 31, w = threadIdx.x >> 5;
#pragma unroll
    for (int o = 16; o; o >>= 1) v += __shfl_down_sync(0xffffffffu, v, o);
    if (!lane) red[w] = v;
    __syncthreads();
    float tot = 0.f;
#pragma unroll
    for (int i = 0; i < 8; i++) tot += red[i];
    __syncthreads();
    return tot;
}

// ---------------- kernel 5: W1, S, partial column sums of S ------------------
__global__ __launch_bounds__(256) void k_w1s(float* __restrict__ outW1a,
                                             float* __restrict__ outS,
                                             float* __restrict__ outW1b) {
    const int blk = blockIdx.x;
    const int t   = threadIdx.x;
    __shared__ float red[8];
    float colacc[4] = {0.f, 0.f, 0.f, 0.f};
    const int row0 = blk * 32;
    for (int r = 0; r < 32; r++) {
        const int row = row0 + r;
        const float rho = g_rho[row];
        const float inv = g_inv[row];
        const float* drow = g_d + (size_t)row * KC;
        float w[4], part = 0.f;
#pragma unroll
        for (int c = 0; c < 4; c++) {
            float dv = drow[t + c * 256];
            float x  = fmaxf(dv - rho, 0.f);
            w[c] = expf(-x * inv);
            part += w[c];
        }
        float rs = blocksum256(part, red);
        float irs = 1.f / rs;
#pragma unroll
        for (int c = 0; c < 4; c++) {
            size_t idx = (size_t)row * KC + t + c * 256;
            float s = w[c] * irs;
            outW1a[idx] = w[c];
            outW1b[idx] = w[c];
            outS[idx]   = s;
            colacc[c]  += s;
        }
    }
#pragma unroll
    for (int c = 0; c < 4; c++)
        g_colpart[(size_t)blk * KC + t + c * 256] = colacc[c];
}

// ---------------- kernel 6: finalize column sums -----------------------------
__global__ void k_colsum() {
    int col = blockIdx.x * blockDim.x + threadIdx.x;
    if (col >= KC) return;
    float s = 0.f;
    for (int b = 0; b < 1024; b++) s += g_colpart[(size_t)b * KC + col];
    g_colsum[col] = s;
}

// ---------------- kernel 7: D = rownorm(S*S / colsum) ------------------------
__global__ __launch_bounds__(256) void k_D(const float* __restrict__ S,
                                           float* __restrict__ outD) {
    const int blk = blockIdx.x;
    const int t   = threadIdx.x;
    __shared__ float cs[1024];
    __shared__ float red[8];
#pragma unroll
    for (int c = 0; c < 4; c++) cs[t + c * 256] = g_colsum[t + c * 256];
    __syncthreads();
    const int row0 = blk * 32;
    for (int r = 0; r < 32; r++) {
        const int row = row0 + r;
        float tv[4], part = 0.f;
#pragma unroll
        for (int c = 0; c < 4; c++) {
            int col = t + c * 256;
            float s = S[(size_t)row * KC + col];
            tv[c] = (s * s) / cs[col];
            part += tv[c];
        }
        float rs = blocksum256(part, red);
        float irs = 1.f / rs;
#pragma unroll
        for (int c = 0; c < 4; c++)
            outD[(size_t)row * KC + t + c * 256] = tv[c] * irs;
    }
}

// ---------------- launch ------------------------------------------------------
extern "C" void kernel_launch(void* const* d_in, const int* in_sizes, int n_in,
                              void* d_out, int out_size) {
    (void)in_sizes; (void)n_in; (void)out_size;
    const float* z  = (const float*)d_in[0];
    const float* mu = (const float*)d_in[1];
    float* out  = (float*)d_out;
    float* oW1a = out;
    float* oS   = out + NKTOT;
    float* oW1b = out + 2 * NKTOT;
    float* oD   = out + 3 * NKTOT;

    cudaFuncSetAttribute(k_gemm_mma, cudaFuncAttributeMaxDynamicSharedMemorySize,
                         SMEM_GEMM);

    k_prep<<<(NN + KC + 7) / 8, 256>>>(z, mu);
    k_gemm_mma<<<dim3(KC / BN, NN / BM), 256, SMEM_GEMM>>>();
    k_top5<<<NN / 8, 256>>>();
    k_sigma<<<NN / 256, 256>>>();
    k_w1s<<<1024, 256>>>(oW1a, oS, oW1b);
    k_colsum<<<4, 256>>>();
    k_D<<<1024, 256>>>(oS, oD);
}

// round 14
// speedup vs baseline: 1.6959x; 1.0051x over previous
#include <cuda_runtime.h>
#include <cuda_bf16.h>
#include <cstdint>
#include <math.h>

#define NN 32768
#define KC 1024
#define DH 512
#define NITERS 80
#define EPS2 2.0e-5f
#define DEPS2 5.12e-8f
#define NKTOT ((size_t)NN * KC)

// GEMM tiling (mma.sync + cp.async double-buffer)
#define BM 128
#define BN 128
#define KCH 32
#define NKCH (DH / KCH)       // 16
#define SPAD 40               // padded smem row stride (bf16): 80B, ldmatrix conflict-free
#define ABYTES 10240          // one array: 128*40*2
#define BUFBYTES 40960        // Ah,Al,Bh,Bl
#define SMEM_GEMM (2 * BUFBYTES)

// ---------------- scratch ----------------------------------------------------
__device__ float g_d[(size_t)NN * KC];
__device__ float g_az[NN];
__device__ float g_bm[KC];
__device__ float g_rel[NN * 5];
__device__ float g_rho[NN];
__device__ float g_inv[NN];
__device__ float g_colpart[1024 * KC];
__device__ float g_colsum[KC];
__device__ __nv_bfloat16 g_zhi[(size_t)NN * DH];
__device__ __nv_bfloat16 g_zlo[(size_t)NN * DH];
__device__ __nv_bfloat16 g_mhi[(size_t)KC * DH];
__device__ __nv_bfloat16 g_mlo[(size_t)KC * DH];

// ---------------- PTX helpers -------------------------------------------------
__device__ __forceinline__ uint32_t smem_u32(const void* p) {
    uint32_t a;
    asm("{ .reg .u64 t; cvta.to.shared.u64 t, %1; cvt.u32.u64 %0, t; }"
        : "=r"(a) : "l"(p));
    return a;
}
#define LDSM_X4(r0, r1, r2, r3, addr) \
    asm volatile("ldmatrix.sync.aligned.m8n8.x4.shared.b16 {%0,%1,%2,%3}, [%4];" \
                 : "=r"(r0), "=r"(r1), "=r"(r2), "=r"(r3) : "r"(addr))
#define MMA16816(d, a, b) \
    asm volatile("mma.sync.aligned.m16n8k16.row.col.f32.bf16.bf16.f32 " \
                 "{%0,%1,%2,%3}, {%4,%5,%6,%7}, {%8,%9}, {%0,%1,%2,%3};" \
                 : "+f"((d)[0]), "+f"((d)[1]), "+f"((d)[2]), "+f"((d)[3]) \
                 : "r"((a)[0]), "r"((a)[1]), "r"((a)[2]), "r"((a)[3]), \
                   "r"((b)[0]), "r"((b)[1]))
#define CP16(dst, src) \
    asm volatile("cp.async.cg.shared.global [%0], [%1], 16;" :: "r"(dst), "l"(src))
#define CP_COMMIT() asm volatile("cp.async.commit_group;")
#define CP_WAIT1()  asm volatile("cp.async.wait_group 1;")
#define CP_WAIT0()  asm volatile("cp.async.wait_group 0;")

// ---------------- kernel 1: fused rownorm + hi/lo split ----------------------
__global__ void k_prep(const float* __restrict__ z, const float* __restrict__ mu) {
    int gw   = (blockIdx.x * blockDim.x + threadIdx.x) >> 5;
    int lane = threadIdx.x & 31;
    if (gw >= NN + KC) return;
    const bool isZ = gw < NN;
    const int r = isZ ? gw : gw - NN;
    const float* base = isZ ? (z + (size_t)r * DH) : (mu + (size_t)r * DH);
    __nv_bfloat16* hd = isZ ? (g_zhi + (size_t)r * DH) : (g_mhi + (size_t)r * DH);
    __nv_bfloat16* ld = isZ ? (g_zlo + (size_t)r * DH) : (g_mlo + (size_t)r * DH);
    float s = 0.f, q = 0.f;
#pragma unroll
    for (int i = 0; i < 4; i++) {
        const int off = lane * 4 + i * 128;
        float4 v = *(const float4*)(base + off);
        s += v.x + v.y + v.z + v.w;
        q += v.x * v.x + v.y * v.y + v.z * v.z + v.w * v.w;
        float x[4] = {v.x, v.y, v.z, v.w};
        uint32_t hp[2], lp[2];
#pragma unroll
        for (int p = 0; p < 2; p++) {
            __nv_bfloat16 h0 = __float2bfloat16(x[p * 2 + 0]);
            __nv_bfloat16 h1 = __float2bfloat16(x[p * 2 + 1]);
            __nv_bfloat16 l0 = __float2bfloat16(x[p * 2 + 0] - __bfloat162float(h0));
            __nv_bfloat16 l1 = __float2bfloat16(x[p * 2 + 1] - __bfloat162float(h1));
            hp[p] = (uint32_t)__bfloat16_as_ushort(h0) | ((uint32_t)__bfloat16_as_ushort(h1) << 16);
            lp[p] = (uint32_t)__bfloat16_as_ushort(l0) | ((uint32_t)__bfloat16_as_ushort(l1) << 16);
        }
        *(uint2*)(hd + off) = make_uint2(hp[0], hp[1]);
        *(uint2*)(ld + off) = make_uint2(lp[0], lp[1]);
    }
#pragma unroll
    for (int o = 16; o; o >>= 1) {
        s += __shfl_down_sync(0xffffffffu, s, o);
        q += __shfl_down_sync(0xffffffffu, q, o);
    }
    if (lane == 0) {
        if (isZ) g_az[r] = q + EPS2 * s;
        else     g_bm[r] = q - EPS2 * s + DEPS2;
    }
}

// ---------------- kernel 2: bf16 3-term mma.sync GEMM, cp.async pipelined ----
__global__ __launch_bounds__(256) void k_gemm_mma() {
    extern __shared__ __align__(16) char smem[];
    const uint32_t sb = smem_u32(smem);

    const int tid  = threadIdx.x;
    const int wid  = tid >> 5;
    const int lane = tid & 31;
    const int bj   = blockIdx.x;
    const int bi   = blockIdx.y;
    const int wm   = wid >> 2;
    const int wn   = wid & 3;

    const __nv_bfloat16* zh = g_zhi + (size_t)(bi * BM) * DH;
    const __nv_bfloat16* zl = g_zlo + (size_t)(bi * BM) * DH;
    const __nv_bfloat16* mh = g_mhi + (size_t)(bj * BN) * DH;
    const __nv_bfloat16* ml = g_mlo + (size_t)(bj * BN) * DH;

    float acc[4][4][4];
#pragma unroll
    for (int mt = 0; mt < 4; mt++)
#pragma unroll
        for (int nt = 0; nt < 4; nt++)
#pragma unroll
            for (int e = 0; e < 4; e++) acc[mt][nt][e] = 0.f;

    const int lr = tid >> 1;
    const int lc = (tid & 1) * 16;
    const uint32_t soRow = (uint32_t)(lr * SPAD + lc) * 2;

    // prologue: load chunk 0 into buffer 0
    {
        const size_t go = (size_t)lr * DH + lc;
        const uint32_t d = sb + soRow;
        CP16(d +            0, zh + go); CP16(d +            16, zh + go + 8);
        CP16(d + ABYTES +   0, zl + go); CP16(d + ABYTES +   16, zl + go + 8);
        CP16(d + 2*ABYTES + 0, mh + go); CP16(d + 2*ABYTES + 16, mh + go + 8);
        CP16(d + 3*ABYTES + 0, ml + go); CP16(d + 3*ABYTES + 16, ml + go + 8);
        CP_COMMIT();
    }

    for (int kc = 0; kc < NKCH; kc++) {
        const int b = kc & 1;
        if (kc + 1 < NKCH) {
            const size_t go = (size_t)lr * DH + (kc + 1) * KCH + lc;
            const uint32_t d = sb + (1 - b) * BUFBYTES + soRow;
            CP16(d +            0, zh + go); CP16(d +            16, zh + go + 8);
            CP16(d + ABYTES +   0, zl + go); CP16(d + ABYTES +   16, zl + go + 8);
            CP16(d + 2*ABYTES + 0, mh + go); CP16(d + 2*ABYTES + 16, mh + go + 8);
            CP16(d + 3*ABYTES + 0, ml + go); CP16(d + 3*ABYTES + 16, ml + go + 8);
            CP_COMMIT();
            CP_WAIT1();
        } else {
            CP_WAIT0();
        }
        __syncthreads();

        const uint32_t bufBase = sb + b * BUFBYTES;
#pragma unroll
        for (int combo = 0; combo < 3; combo++) {
            const uint32_t aBase = bufBase + ((combo < 2) ? 0u : (uint32_t)ABYTES);
            const uint32_t bBase = bufBase + ((combo == 1) ? 3u : 2u) * (uint32_t)ABYTES;
#pragma unroll
            for (int k16 = 0; k16 < KCH; k16 += 16) {
                uint32_t af[4][4];
#pragma unroll
                for (int mt = 0; mt < 4; mt++) {
                    const int mrow = wm * 64 + mt * 16 + (lane & 15);
                    const int mcol = k16 + (lane >> 4) * 8;
                    LDSM_X4(af[mt][0], af[mt][1], af[mt][2], af[mt][3],
                            aBase + (uint32_t)(mrow * SPAD + mcol) * 2);
                }
                uint32_t bf[4][2];
#pragma unroll
                for (int np = 0; np < 2; np++) {
                    const int nrow = wn * 32 + np * 16 + (lane & 7) + ((lane >> 4) & 1) * 8;
                    const int ncol = k16 + ((lane >> 3) & 1) * 8;
                    uint32_t q0, q1, q2, q3;
                    LDSM_X4(q0, q1, q2, q3,
                            bBase + (uint32_t)(nrow * SPAD + ncol) * 2);
                    bf[np * 2 + 0][0] = q0; bf[np * 2 + 0][1] = q1;
                    bf[np * 2 + 1][0] = q2; bf[np * 2 + 1][1] = q3;
                }
#pragma unroll
                for (int mt = 0; mt < 4; mt++)
#pragma unroll
                    for (int nt = 0; nt < 4; nt++)
                        MMA16816(acc[mt][nt], af[mt], bf[nt]);
            }
        }
        __syncthreads();
    }

    // epilogue: d = sqrt(max(az + bm - 2*acc, 0))
    const int g  = lane >> 2;
    const int nc = (lane & 3) * 2;
    const int row0 = bi * BM + wm * 64;
    const int col0 = bj * BN + wn * 32;
#pragma unroll
    for (int mt = 0; mt < 4; mt++) {
        const int r0 = row0 + mt * 16 + g;
        const int r1 = r0 + 8;
        const float az0 = g_az[r0];
        const float az1 = g_az[r1];
#pragma unroll
        for (int nt = 0; nt < 4; nt++) {
            const int c = col0 + nt * 8 + nc;
            const float bm0 = g_bm[c];
            const float bm1 = g_bm[c + 1];
            const float* a = acc[mt][nt];
            float2 o0, o1;
            o0.x = sqrtf(fmaxf(az0 + bm0 - 2.f * a[0], 0.f));
            o0.y = sqrtf(fmaxf(az0 + bm1 - 2.f * a[1], 0.f));
            o1.x = sqrtf(fmaxf(az1 + bm0 - 2.f * a[2], 0.f));
            o1.y = sqrtf(fmaxf(az1 + bm1 - 2.f * a[3], 0.f));
            *(float2*)(g_d + (size_t)r0 * KC + c) = o0;
            *(float2*)(g_d + (size_t)r1 * KC + c) = o1;
        }
    }
}

// ---------------- top-5 insertion helper -------------------------------------
__device__ __forceinline__ void ins5(float v, float& t0, float& t1, float& t2,
                                     float& t3, float& t4) {
    if (v < t4) {
        if (v < t3) {
            t4 = t3;
            if (v < t2) {
                t3 = t2;
                if (v < t1) {
                    t2 = t1;
                    if (v < t0) { t1 = t0; t0 = v; } else t1 = v;
                } else t2 = v;
            } else t3 = v;
        } else t4 = v;
    }
}

// ---------------- kernel 3: 5 smallest per row (warp per row) ----------------
__global__ __launch_bounds__(256) void k_top5() {
    const int row  = (blockIdx.x * blockDim.x + threadIdx.x) >> 5;
    const int lane = threadIdx.x & 31;
    const float INF = __int_as_float(0x7f800000);
    const float4* dr = (const float4*)(g_d + (size_t)row * KC);
    float t0 = INF, t1 = INF, t2 = INF, t3 = INF, t4 = INF;
#pragma unroll
    for (int i = 0; i < 8; i++) {
        float4 v = dr[lane + i * 32];
        ins5(v.x, t0, t1, t2, t3, t4);
        ins5(v.y, t0, t1, t2, t3, t4);
        ins5(v.z, t0, t1, t2, t3, t4);
        ins5(v.w, t0, t1, t2, t3, t4);
    }
#pragma unroll
    for (int o = 16; o; o >>= 1) {
        float b0 = __shfl_down_sync(0xffffffffu, t0, o);
        float b1 = __shfl_down_sync(0xffffffffu, t1, o);
        float b2 = __shfl_down_sync(0xffffffffu, t2, o);
        float b3 = __shfl_down_sync(0xffffffffu, t3, o);
        float b4 = __shfl_down_sync(0xffffffffu, t4, o);
        ins5(b0, t0, t1, t2, t3, t4);
        ins5(b1, t0, t1, t2, t3, t4);
        ins5(b2, t0, t1, t2, t3, t4);
        ins5(b3, t0, t1, t2, t3, t4);
        ins5(b4, t0, t1, t2, t3, t4);
    }
    if (lane == 0) {
        g_rel[row * 5 + 0] = t0;
        g_rel[row * 5 + 1] = t1;
        g_rel[row * 5 + 2] = t2;
        g_rel[row * 5 + 3] = t3;
        g_rel[row * 5 + 4] = t4;
    }
}

// ---------------- kernel 4: bisection for sigma_z ----------------------------
__global__ void k_sigma() {
    int i = blockIdx.x * blockDim.x + threadIdx.x;
    if (i >= NN) return;
    float r0 = g_rel[i * 5 + 0];
    float e1 = fmaxf(g_rel[i * 5 + 1] - r0, 0.f);
    float e2 = fmaxf(g_rel[i * 5 + 2] - r0, 0.f);
    float e3 = fmaxf(g_rel[i * 5 + 3] - r0, 0.f);
    float e4 = fmaxf(g_rel[i * 5 + 4] - r0, 0.f);
    float m0 = 0.f, m1 = 10000.f, s = 1.f;
    for (int it = 0; it < NITERS; it++) {
        float inv = 1.f / s;
        float cur = 1.f + expf(-e1 * inv) + expf(-e2 * inv)
                        + expf(-e3 * inv) + expf(-e4 * inv);
        if (cur > 1.5f) m1 = s; else m0 = s;
        s = 0.5f * (m0 + m1);
    }
    g_rho[i] = r0;
    g_inv[i] = 1.f / s;
}

__device__ __forceinline__ float blocksum256(float v, float* red) {
    int lane = threadIdx.x & 31, w = threadIdx.x >> 5;
#pragma unroll
    for (int o = 16; o; o >>= 1) v += __shfl_down_sync(0xffffffffu, v, o);
    if (!lane) red[w] = v;
    __syncthreads();
    float tot = 0.f;
#pragma unroll
    for (int i = 0; i < 8; i++) tot += red[i];
    __syncthreads();
    return tot;
}

// ---------------- kernel 5: W1, S, partial column sums of S ------------------
__global__ __launch_bounds__(256) void k_w1s(float* __restrict__ outW1a,
                                             float* __restrict__ outS,
                                             float* __restrict__ outW1b) {
    const int blk = blockIdx.x;
    const int t   = threadIdx.x;
    __shared__ float red[8];
    float colacc[4] = {0.f, 0.f, 0.f, 0.f};
    const int row0 = blk * 32;
    for (int r = 0; r < 32; r++) {
        const int row = row0 + r;
        const float rho = g_rho[row];
        const float inv = g_inv[row];
        const float* drow = g_d + (size_t)row * KC;
        float w[4], part = 0.f;
#pragma unroll
        for (int c = 0; c < 4; c++) {
            float dv = drow[t + c * 256];
            float x  = fmaxf(dv - rho, 0.f);
            w[c] = expf(-x * inv);
            part += w[c];
        }
        float rs = blocksum256(part, red);
        float irs = 1.f / rs;
#pragma unroll
        for (int c = 0; c < 4; c++) {
            size_t idx = (size_t)row * KC + t + c * 256;
            float s = w[c] * irs;
            outW1a[idx] = w[c];
            outW1b[idx] = w[c];
            outS[idx]   = s;
            colacc[c]  += s;
        }
    }
#pragma unroll
    for (int c = 0; c < 4; c++)
        g_colpart[(size_t)blk * KC + t + c * 256] = colacc[c];
}

// ---------------- kernel 6: finalize column sums -----------------------------
__global__ void k_colsum() {
    int col = blockIdx.x * blockDim.x + threadIdx.x;
    if (col >= KC) return;
    float s = 0.f;
    for (int b = 0; b < 1024; b++) s += g_colpart[(size_t)b * KC + col];
    g_colsum[col] = s;
}

// ---------------- kernel 7: D = rownorm(S*S / colsum) ------------------------
__global__ __launch_bounds__(256) void k_D(const float* __restrict__ S,
                                           float* __restrict__ outD) {
    const int blk = blockIdx.x;
    const int t   = threadIdx.x;
    __shared__ float cs[1024];
    __shared__ float red[8];
#pragma unroll
    for (int c = 0; c < 4; c++) cs[t + c * 256] = g_colsum[t + c * 256];
    __syncthreads();
    const int row0 = blk * 32;
    for (int r = 0; r < 32; r++) {
        const int row = row0 + r;
        float tv[4], part = 0.f;
#pragma unroll
        for (int c = 0; c < 4; c++) {
            int col = t + c * 256;
            float s = S[(size_t)row * KC + col];
            tv[c] = (s * s) / cs[col];
            part += tv[c];
        }
        float rs = blocksum256(part, red);
        float irs = 1.f / rs;
#pragma unroll
        for (int c = 0; c < 4; c++)
            outD[(size_t)row * KC + t + c * 256] = tv[c] * irs;
    }
}

// ---------------- launch ------------------------------------------------------
extern "C" void kernel_launch(void* const* d_in, const int* in_sizes, int n_in,
                              void* d_out, int out_size) {
    (void)in_sizes; (void)n_in; (void)out_size;
    const float* z  = (const float*)d_in[0];
    const float* mu = (const float*)d_in[1];
    float* out  = (float*)d_out;
    float* oW1a = out;
    float* oS   = out + NKTOT;
    float* oW1b = out + 2 * NKTOT;
    float* oD   = out + 3 * NKTOT;

    cudaFuncSetAttribute(k_gemm_mma, cudaFuncAttributeMaxDynamicSharedMemorySize,
                         SMEM_GEMM);

    k_prep<<<(NN + KC + 7) / 8, 256>>>(z, mu);
    k_gemm_mma<<<dim3(KC / BN, NN / BM), 256, SMEM_GEMM>>>();
    k_top5<<<NN / 8, 256>>>();
    k_sigma<<<NN / 256, 256>>>();
    k_w1s<<<1024, 256>>>(oW1a, oS, oW1b);
    k_colsum<<<4, 256>>>();
    k_D<<<1024, 256>>>(oS, oD);
}